// round 10
// baseline (speedup 1.0000x reference)
#include <cuda_runtime.h>

#define B_ 8
#define L_ 1024
#define L4_ 256
#define T_ 10
#define TILE 32
#define NTRI 528            // 32*33/2 upper-triangle tile pairs
#define SP 33               // padded shared stride (floats)
#define S_CONST 2.1972245773362196f   // log(9)

// Scratch (__device__ globals: allocation-free rule)
__device__ float g_uu[(size_t)B_*L_*L_];
__device__ float g_us[(size_t)B_*L_*L_];   // uu + uu^T (timestep-invariant)
__device__ float g_m [(size_t)B_*L_*L_];   // 0.5 * m   (timestep-invariant)
__device__ float g_ah[(size_t)B_*L_*L_];
__device__ float g_rowsum[B_*L_];
__device__ float g_lmbd[B_*L_];
__device__ float g_g[B_*L_];

__constant__ float c_aW1[T_*9], c_ab1[T_*3], c_aW2[T_*3], c_ab2[T_];
__constant__ float c_rW1[T_*9], c_rb1[T_*3], c_rW2[T_*3], c_rb2[T_];

__device__ __forceinline__ float sigm(float x){ return 1.0f/(1.0f+__expf(-x)); }

// p = tj*(tj+1)/2 + ti with ti <= tj
__device__ __forceinline__ void tri_decode(int p, int& ti, int& tj){
    int a = (int)((sqrtf(8.0f*(float)p + 1.0f) - 1.0f) * 0.5f);
    while ((a+1)*(a+2)/2 <= p) a++;
    while (a*(a+1)/2 > p) a--;
    tj = a; ti = p - a*(a+1)/2;
}

__device__ __forceinline__ float mlp3(float f0,float f1,float f2,
                                      const float* W1,const float* b1,
                                      const float* W2,float b2){
    float h0=fmaxf(fmaf(W1[0],f0,fmaf(W1[1],f1,fmaf(W1[2],f2,b1[0]))),0.f);
    float h1=fmaxf(fmaf(W1[3],f0,fmaf(W1[4],f1,fmaf(W1[5],f2,b1[1]))),0.f);
    float h2=fmaxf(fmaf(W1[6],f0,fmaf(W1[7],f1,fmaf(W1[8],f2,b1[2]))),0.f);
    return fmaxf(fmaf(W2[0],h0,fmaf(W2[1],h1,fmaf(W2[2],h2,b2))),0.f);
}

__device__ __forceinline__ float dot4(float4 a, float4 b){
    return fmaf(a.x,b.x, fmaf(a.y,b.y, fmaf(a.z,b.z, a.w*b.w)));
}

__global__ void k_zero_rowsum(){
    int i = blockIdx.x*blockDim.x + threadIdx.x;
    if (i < B_*L_) g_rowsum[i] = 0.f;
}

// ---------------------------------------------------------------------------
// Init: uu, ah, us = uu+uu^T, mh = 0.5*m, rowsum0
// ---------------------------------------------------------------------------
__global__ __launch_bounds__(256) void k_init(const float4* __restrict__ u4,
                                              const float4* __restrict__ x4){
    int b = blockIdx.y;
    int ti, tj; tri_decode(blockIdx.x, ti, tj);
    bool diag = (ti == tj);
    __shared__ float s_uuA[TILE*SP], s_uuB[TILE*SP];
    __shared__ float s_ahA[TILE*SP], s_ahB[TILE*SP];
    __shared__ float4 s_cI[TILE], s_cJ[TILE];

    int tid = threadIdx.x;
    int r  = tid >> 3;
    int l8 = tid & 7;
    int c0 = l8 * 4;

    if (tid < 64){
        int q = tid & 31;
        int rowg = ((tid < 32) ? tj : ti)*TILE + q;
        float4 xr = x4[b*L_ + rowg];
        float4 c = make_float4(xr.y, xr.x + xr.w, xr.w, xr.y + xr.z);
        if (tid < 32) s_cJ[q] = c; else s_cI[q] = c;
    }

    int iA = (b*L_ + ti*TILE + r)*L4_ + tj*8 + l8;
    int iB = (b*L_ + tj*TILE + r)*L4_ + ti*8 + l8;

    float4* uu4 = reinterpret_cast<float4*>(g_uu);
    float4* ah4 = reinterpret_cast<float4*>(g_ah);
    float4* us4 = reinterpret_cast<float4*>(g_us);
    float4* mh4 = reinterpret_cast<float4*>(g_m);

    float uuAa[4], ahAa[4], uuBa[4], ahBa[4];
    {
        float4 uv = u4[iA];
        float ua[4] = {uv.x, uv.y, uv.z, uv.w};
        #pragma unroll
        for (int s=0;s<4;s++){
            float uu = sigm(2.f*(ua[s]-S_CONST))*ua[s];
            float ah = sigm(uu)*sigm(2.f*(uu-S_CONST));
            uuAa[s]=uu; ahAa[s]=ah;
            s_uuA[r*SP + c0 + s] = uu;
            s_ahA[r*SP + c0 + s] = ah;
        }
        uu4[iA] = make_float4(uuAa[0],uuAa[1],uuAa[2],uuAa[3]);
        ah4[iA] = make_float4(ahAa[0],ahAa[1],ahAa[2],ahAa[3]);
    }
    if (!diag){
        float4 uv = u4[iB];
        float ua[4] = {uv.x, uv.y, uv.z, uv.w};
        #pragma unroll
        for (int s=0;s<4;s++){
            float uu = sigm(2.f*(ua[s]-S_CONST))*ua[s];
            float ah = sigm(uu)*sigm(2.f*(uu-S_CONST));
            uuBa[s]=uu; ahBa[s]=ah;
            s_uuB[r*SP + c0 + s] = uu;
            s_ahB[r*SP + c0 + s] = ah;
        }
        uu4[iB] = make_float4(uuBa[0],uuBa[1],uuBa[2],uuBa[3]);
        ah4[iB] = make_float4(ahBa[0],ahBa[1],ahBa[2],ahBa[3]);
    }
    float4 xiA = x4[b*L_ + ti*TILE + r];
    float4 xiB = x4[b*L_ + tj*TILE + r];
    __syncthreads();

    float sumA = 0.f, sumB = 0.f;
    {
        float mv[4], uv[4];
        #pragma unroll
        for (int s=0;s<4;s++){
            float mh = 0.5f * dot4(xiA, s_cJ[c0+s]);
            float uji = (diag ? s_uuA : s_uuB)[(c0+s)*SP + r];
            float aji = (diag ? s_ahA : s_ahB)[(c0+s)*SP + r];
            mv[s] = mh;
            uv[s] = uuAa[s] + uji;
            sumA += mh * fmaf(ahAa[s], ahAa[s], aji*aji);
        }
        mh4[iA] = make_float4(mv[0],mv[1],mv[2],mv[3]);
        us4[iA] = make_float4(uv[0],uv[1],uv[2],uv[3]);
    }
    if (!diag){
        float mv[4], uv[4];
        #pragma unroll
        for (int s=0;s<4;s++){
            float mh = 0.5f * dot4(xiB, s_cI[c0+s]);
            float uji = s_uuA[(c0+s)*SP + r];
            float aji = s_ahA[(c0+s)*SP + r];
            mv[s] = mh;
            uv[s] = uuBa[s] + uji;
            sumB += mh * fmaf(ahBa[s], ahBa[s], aji*aji);
        }
        mh4[iB] = make_float4(mv[0],mv[1],mv[2],mv[3]);
        us4[iB] = make_float4(uv[0],uv[1],uv[2],uv[3]);
    }
    #pragma unroll
    for (int o=1;o<8;o<<=1){
        sumA += __shfl_xor_sync(0xffffffffu, sumA, o);
        sumB += __shfl_xor_sync(0xffffffffu, sumB, o);
    }
    if (l8 == 0){
        atomicAdd(&g_rowsum[b*L_ + ti*TILE + r], sumA);
        if (!diag) atomicAdd(&g_rowsum[b*L_ + tj*TILE + r], sumB);
    }
}

__global__ void k_lam0(){
    int i = blockIdx.x*blockDim.x + threadIdx.x;
    if (i < B_*L_){
        float rs = g_rowsum[i];
        float l = fmaxf(rs - 1.f, 0.f);           // W_PEN = 1
        g_lmbd[i] = l;
        g_g[i] = l * sigm(2.f*(rs - 1.f));
        g_rowsum[i] = 0.f;
    }
}

__global__ void k_lam(const float* __restrict__ lW1,const float* __restrict__ lb1,
                      const float* __restrict__ lW2,const float* __restrict__ lb2,int t){
    int i = blockIdx.x*blockDim.x + threadIdx.x;
    if (i < B_*L_){
        float rs = g_rowsum[i];
        float lg = fmaxf(rs - 1.f, 0.f);
        float l0 = g_lmbd[i];
        const float* W1 = lW1 + t*6;
        const float* b1 = lb1 + t*3;
        const float* W2 = lW2 + t*3;
        float h0 = fmaxf(fmaf(W1[0],l0,fmaf(W1[1],lg,b1[0])),0.f);
        float h1 = fmaxf(fmaf(W1[2],l0,fmaf(W1[3],lg,b1[1])),0.f);
        float h2 = fmaxf(fmaf(W1[4],l0,fmaf(W1[5],lg,b1[2])),0.f);
        float ln = fmaxf(fmaf(W2[0],h0,fmaf(W2[1],h1,fmaf(W2[2],h2,__ldg(lb2+t)))),0.f);
        g_lmbd[i] = ln;
        g_g[i] = ln * sigm(2.f*(rs - 1.f));
        g_rowsum[i] = 0.f;
    }
}

// ---------------------------------------------------------------------------
// Per-timestep fused step: block owns tile pair (I,J)+(J,I).
// grad = ah * mh * (2*(gI+gJ) - us);  a = mh * (an_ij^2 + an_ji^2)
// ---------------------------------------------------------------------------
__global__ __launch_bounds__(256) void k_step(int t, int last,
                                              float4* __restrict__ out4base){
    int b = blockIdx.y;
    int ti, tj; tri_decode(blockIdx.x, ti, tj);
    bool diag = (ti == tj);
    __shared__ float s_anA[TILE*SP], s_anB[TILE*SP];
    __shared__ __align__(16) float s_gI[TILE];
    __shared__ __align__(16) float s_gJ[TILE];

    int tid = threadIdx.x;
    int r  = tid >> 3;
    int l8 = tid & 7;
    int c0 = l8 * 4;

    if (tid < 64){
        int q = tid & 31;
        int rowg = ((tid < 32) ? tj : ti)*TILE + q;
        float gv = g_g[b*L_ + rowg];
        if (tid < 32) s_gJ[q] = gv; else s_gI[q] = gv;
    }

    int iA = (b*L_ + ti*TILE + r)*L4_ + tj*8 + l8;
    int iB = (b*L_ + tj*TILE + r)*L4_ + ti*8 + l8;

    const float4* uu4 = reinterpret_cast<const float4*>(g_uu);
    const float4* us4 = reinterpret_cast<const float4*>(g_us);
    const float4* mh4 = reinterpret_cast<const float4*>(g_m);
    const float4* ah4 = reinterpret_cast<const float4*>(g_ah);
    float4* ahw4 = reinterpret_cast<float4*>(g_ah);

    float4 uuA = uu4[iA], usA = us4[iA], mAv = mh4[iA], ahA = ah4[iA];
    float4 uuB, usB, mBv, ahB;
    if (!diag){ uuB = uu4[iB]; usB = us4[iB]; mBv = mh4[iB]; ahB = ah4[iB]; }
    __syncthreads();

    float gIr = s_gI[r], gJr = s_gJ[r];
    float4 gj = reinterpret_cast<const float4*>(s_gJ)[l8];
    float4 gi = reinterpret_cast<const float4*>(s_gI)[l8];

    const float* aW1 = &c_aW1[t*9]; const float* ab1 = &c_ab1[t*3];
    const float* aW2 = &c_aW2[t*3]; float ab2 = c_ab2[t];
    const float* rW1 = &c_rW1[t*9]; const float* rb1 = &c_rb1[t*3];
    const float* rW2 = &c_rW2[t*3]; float rb2 = c_rb2[t];

    float mAa[4] = {mAv.x, mAv.y, mAv.z, mAv.w};
    float mBa[4];
    float anA[4], anB[4];

    // Phase A: new a_hat (orientation A)
    {
        float uua[4] = {uuA.x, uuA.y, uuA.z, uuA.w};
        float usa[4] = {usA.x, usA.y, usA.z, usA.w};
        float aha[4] = {ahA.x, ahA.y, ahA.z, ahA.w};
        float gja[4] = {gj.x, gj.y, gj.z, gj.w};
        #pragma unroll
        for (int s=0;s<4;s++){
            float gf2 = fmaf(2.f, gIr + gja[s], -usa[s]);
            float grad = aha[s] * mAa[s] * gf2;
            float v   = mlp3(aha[s], grad, uua[s], aW1, ab1, aW2, ab2);
            float rho = mlp3(aha[s], grad, uua[s], rW1, rb1, rW2, rb2);
            float an = fminf(fmaxf(v - rho, 0.f), 1.f);
            anA[s] = an;
            s_anA[r*SP + c0 + s] = an;
        }
        if (!last) ahw4[iA] = make_float4(anA[0], anA[1], anA[2], anA[3]);
    }
    if (!diag){
        mBa[0]=mBv.x; mBa[1]=mBv.y; mBa[2]=mBv.z; mBa[3]=mBv.w;
        float uua[4] = {uuB.x, uuB.y, uuB.z, uuB.w};
        float usa[4] = {usB.x, usB.y, usB.z, usB.w};
        float aha[4] = {ahB.x, ahB.y, ahB.z, ahB.w};
        float gia[4] = {gi.x, gi.y, gi.z, gi.w};
        #pragma unroll
        for (int s=0;s<4;s++){
            float gf2 = fmaf(2.f, gJr + gia[s], -usa[s]);
            float grad = aha[s] * mBa[s] * gf2;
            float v   = mlp3(aha[s], grad, uua[s], aW1, ab1, aW2, ab2);
            float rho = mlp3(aha[s], grad, uua[s], rW1, rb1, rW2, rb2);
            float an = fminf(fmaxf(v - rho, 0.f), 1.f);
            anB[s] = an;
            s_anB[r*SP + c0 + s] = an;
        }
        if (!last) ahw4[iB] = make_float4(anB[0], anB[1], anB[2], anB[3]);
    }
    __syncthreads();

    // Phase B: a = mh*(an^2 + an_T^2) -> out, rowsums
    float4* o4 = out4base + (size_t)t*(B_*L_*L4_);
    float sumA = 0.f, sumB = 0.f;
    {
        float av[4];
        #pragma unroll
        for (int s=0;s<4;s++){
            float aji = (diag ? s_anA : s_anB)[(c0+s)*SP + r];
            float a = mAa[s] * fmaf(anA[s], anA[s], aji*aji);
            av[s] = a; sumA += a;
        }
        __stcs(&o4[iA], make_float4(av[0],av[1],av[2],av[3]));
    }
    if (!diag){
        float av[4];
        #pragma unroll
        for (int s=0;s<4;s++){
            float aji = s_anA[(c0+s)*SP + r];
            float a = mBa[s] * fmaf(anB[s], anB[s], aji*aji);
            av[s] = a; sumB += a;
        }
        __stcs(&o4[iB], make_float4(av[0],av[1],av[2],av[3]));
    }
    if (!last){
        #pragma unroll
        for (int o=1;o<8;o<<=1){
            sumA += __shfl_xor_sync(0xffffffffu, sumA, o);
            sumB += __shfl_xor_sync(0xffffffffu, sumB, o);
        }
        if (l8 == 0){
            atomicAdd(&g_rowsum[b*L_ + ti*TILE + r], sumA);
            if (!diag) atomicAdd(&g_rowsum[b*L_ + tj*TILE + r], sumB);
        }
    }
}

extern "C" void kernel_launch(void* const* d_in, const int* in_sizes, int n_in,
                              void* d_out, int out_size){
    const float* u = (const float*)d_in[0];
    const float* x = (const float*)d_in[1];
    int wb = 2;
    if (n_in >= 15 && in_sizes[2] == 1) wb = 3;
    const float* aW1 = (const float*)d_in[wb+0];
    const float* ab1 = (const float*)d_in[wb+1];
    const float* aW2 = (const float*)d_in[wb+2];
    const float* ab2 = (const float*)d_in[wb+3];
    const float* rW1 = (const float*)d_in[wb+4];
    const float* rb1 = (const float*)d_in[wb+5];
    const float* rW2 = (const float*)d_in[wb+6];
    const float* rb2 = (const float*)d_in[wb+7];
    const float* lW1 = (const float*)d_in[wb+8];
    const float* lb1 = (const float*)d_in[wb+9];
    const float* lW2 = (const float*)d_in[wb+10];
    const float* lb2 = (const float*)d_in[wb+11];
    float* out = (float*)d_out;

    cudaMemcpyToSymbolAsync(c_aW1, aW1, T_*9*sizeof(float), 0, cudaMemcpyDeviceToDevice, 0);
    cudaMemcpyToSymbolAsync(c_ab1, ab1, T_*3*sizeof(float), 0, cudaMemcpyDeviceToDevice, 0);
    cudaMemcpyToSymbolAsync(c_aW2, aW2, T_*3*sizeof(float), 0, cudaMemcpyDeviceToDevice, 0);
    cudaMemcpyToSymbolAsync(c_ab2, ab2, T_*1*sizeof(float), 0, cudaMemcpyDeviceToDevice, 0);
    cudaMemcpyToSymbolAsync(c_rW1, rW1, T_*9*sizeof(float), 0, cudaMemcpyDeviceToDevice, 0);
    cudaMemcpyToSymbolAsync(c_rb1, rb1, T_*3*sizeof(float), 0, cudaMemcpyDeviceToDevice, 0);
    cudaMemcpyToSymbolAsync(c_rW2, rW2, T_*3*sizeof(float), 0, cudaMemcpyDeviceToDevice, 0);
    cudaMemcpyToSymbolAsync(c_rb2, rb2, T_*1*sizeof(float), 0, cudaMemcpyDeviceToDevice, 0);

    dim3 grid(NTRI, B_);
    k_zero_rowsum<<<(B_*L_+255)/256, 256>>>();
    k_init<<<grid, 256>>>((const float4*)u, (const float4*)x);
    k_lam0<<<(B_*L_+255)/256, 256>>>();
    for (int t=0; t<T_; t++){
        k_step<<<grid, 256>>>(t, (t==T_-1) ? 1 : 0, (float4*)out);
        if (t+1 < T_)
            k_lam<<<(B_*L_+255)/256, 256>>>(lW1, lb1, lW2, lb2, t);
    }
    (void)out_size;
}